// round 5
// baseline (speedup 1.0000x reference)
#include <cuda_runtime.h>
#include <cuda_bf16.h>

// Problem constants
#define PB   2
#define PS   1024
#define PHQ  32
#define PHKV 8
#define PG   (PHQ / PHKV)   // 4
#define PD   128

#define BM 128
#define BN 64
#define NT 256              // 8 warps; each warp owns a 16-row stripe

#define SCALE 0.08838834764831845f
#define NEGINF (-1e30f)

#define STR 136             // bf16 smem row stride (128 + 8 pad) -> conflict-free ldmatrix

// smem offsets in bf16 elements
#define SM_QH 0
#define SM_QL (BM * STR)                        // 17408
#define SM_KV (2 * BM * STR)                    // 34816
#define SM_ST(s, a) (SM_KV + ((s) * 4 + (a)) * (BN * STR))
#define SM_TOT (SM_KV + 8 * BN * STR)           // 104448 bf16
#define SMEM_BYTES (SM_TOT * 2)                 // 208896 bytes

// Pre-split K/V scratch (bf16 hi/lo), layout [b, s, hkv, d]
#define KV_ELEMS (PB * PS * PHKV * PD)          // 2097152
__device__ __nv_bfloat16 g_khi[KV_ELEMS];
__device__ __nv_bfloat16 g_klo[KV_ELEMS];
__device__ __nv_bfloat16 g_vhi[KV_ELEMS];
__device__ __nv_bfloat16 g_vlo[KV_ELEMS];

// ---------------------------------------------------------------------------
// PTX helpers
// ---------------------------------------------------------------------------
__device__ __forceinline__ void ldsm4(unsigned* r, unsigned addr) {
    asm volatile("ldmatrix.sync.aligned.m8n8.x4.shared.b16 {%0,%1,%2,%3}, [%4];"
                 : "=r"(r[0]), "=r"(r[1]), "=r"(r[2]), "=r"(r[3]) : "r"(addr));
}
__device__ __forceinline__ void ldsm4t(unsigned* r, unsigned addr) {
    asm volatile("ldmatrix.sync.aligned.m8n8.x4.trans.shared.b16 {%0,%1,%2,%3}, [%4];"
                 : "=r"(r[0]), "=r"(r[1]), "=r"(r[2]), "=r"(r[3]) : "r"(addr));
}
__device__ __forceinline__ void mma_bf16(float* c, const unsigned* a, const unsigned* b) {
    asm volatile(
        "mma.sync.aligned.m16n8k16.row.col.f32.bf16.bf16.f32 "
        "{%0,%1,%2,%3}, {%4,%5,%6,%7}, {%8,%9}, {%0,%1,%2,%3};"
        : "+f"(c[0]), "+f"(c[1]), "+f"(c[2]), "+f"(c[3])
        : "r"(a[0]), "r"(a[1]), "r"(a[2]), "r"(a[3]), "r"(b[0]), "r"(b[1]));
}
__device__ __forceinline__ void cpa16(unsigned dst, const void* src) {
    asm volatile("cp.async.cg.shared.global [%0], [%1], 16;" :: "r"(dst), "l"(src));
}
#define CP_COMMIT()  asm volatile("cp.async.commit_group;" ::: "memory")
#define CP_WAIT(N)   asm volatile("cp.async.wait_group %0;" :: "n"(N) : "memory")

// Split fp32 pair into (hi, lo) bf16x2 packed registers: x = hi + lo
__device__ __forceinline__ void split2(float x0, float x1, unsigned& hi, unsigned& lo) {
    __nv_bfloat16 h0 = __float2bfloat16(x0);
    __nv_bfloat16 h1 = __float2bfloat16(x1);
    float r0 = x0 - __bfloat162float(h0);
    float r1 = x1 - __bfloat162float(h1);
    __nv_bfloat162 H(h0, h1);
    __nv_bfloat162 L(__float2bfloat16(r0), __float2bfloat16(r1));
    hi = *reinterpret_cast<unsigned*>(&H);
    lo = *reinterpret_cast<unsigned*>(&L);
}

// ---------------------------------------------------------------------------
// Pre-pass: split K and V into (hi, lo) bf16 scratch. Grid covers 2x524288 f4.
// ---------------------------------------------------------------------------
__global__ void split_kv_kernel(const float* __restrict__ xk,
                                const float* __restrict__ xv)
{
    int idx = blockIdx.x * blockDim.x + threadIdx.x;     // 0 .. 2*524288-1
    int half = idx >> 19;
    int i = idx & 524287;
    float4 v = ((const float4*)(half ? xv : xk))[i];
    unsigned h01, l01, h23, l23;
    split2(v.x, v.y, h01, l01);
    split2(v.z, v.w, h23, l23);
    __nv_bfloat16* hi = half ? g_vhi : g_khi;
    __nv_bfloat16* lo = half ? g_vlo : g_klo;
    int e = i * 4;
    *(unsigned*)(hi + e)     = h01;
    *(unsigned*)(hi + e + 2) = h23;
    *(unsigned*)(lo + e)     = l01;
    *(unsigned*)(lo + e + 2) = l23;
}

// ---------------------------------------------------------------------------
// Flash attention, tensor-core path, cp.async double-buffered K/V pipeline.
// One CTA per (q-tile=128, head, batch). 8 warps; warp w owns rows [16w,16w+16).
// ---------------------------------------------------------------------------
__global__ __launch_bounds__(NT)
void attn_kernel(const float* __restrict__ xq, float* __restrict__ out)
{
    extern __shared__ __nv_bfloat16 sm[];
    const unsigned smb = (unsigned)__cvta_generic_to_shared(sm);

    const int qt = blockIdx.x;
    const int h  = blockIdx.y;
    const int b  = blockIdx.z;
    const int hk = h / PG;
    const int tid  = threadIdx.x;
    const int lane = tid & 31;
    const int wid  = tid >> 5;
    const int q0 = qt * BM;
    const int m0 = wid * 16;
    const int nk = 2 * qt + 2;   // k-tiles of 64 covering causal span

    // ---- Prologue: issue cp.async for K/V tile 0 (stage 0), one group ----
    {
        const size_t kvoff = ((size_t)(b * PS + 0) * PHKV + hk) * PD;
        const __nv_bfloat16* gsrc[4] = { g_khi + kvoff, g_klo + kvoff,
                                         g_vhi + kvoff, g_vlo + kvoff };
        #pragma unroll
        for (int a = 0; a < 4; ++a)
            #pragma unroll
            for (int it = 0; it < 4; ++it) {
                int ci = tid + it * NT;     // 0..1023
                int r = ci >> 4, c = ci & 15;
                cpa16(smb + (SM_ST(0, a) + r * STR + c * 8) * 2,
                      gsrc[a] + (size_t)r * (PHKV * PD) + c * 8);
            }
        CP_COMMIT();
    }

    // ---- Load + split Q tile (pre-scaled) into smem (regular stores) ----
    {
        const float* qbase = xq + ((size_t)(b * PS + q0) * PHQ + h) * PD;
        #pragma unroll
        for (int it = 0; it < (BM * PD / 4) / NT; ++it) {   // 16 iters
            int idx = tid + it * NT;
            int r = idx >> 5;
            int c4 = idx & 31;
            float4 v = *(const float4*)(qbase + (size_t)r * (PHQ * PD) + c4 * 4);
            v.x *= SCALE; v.y *= SCALE; v.z *= SCALE; v.w *= SCALE;
            unsigned h01, l01, h23, l23;
            split2(v.x, v.y, h01, l01);
            split2(v.z, v.w, h23, l23);
            int o = r * STR + c4 * 4;
            *(unsigned*)(sm + SM_QH + o)     = h01;
            *(unsigned*)(sm + SM_QH + o + 2) = h23;
            *(unsigned*)(sm + SM_QL + o)     = l01;
            *(unsigned*)(sm + SM_QL + o + 2) = l23;
        }
    }

    // Output accumulators: 16 n-blocks of m16n8 C-frags
    float oc[16][4];
    #pragma unroll
    for (int nb = 0; nb < 16; ++nb)
        #pragma unroll
        for (int j = 0; j < 4; ++j) oc[nb][j] = 0.f;
    float mr0 = NEGINF, mr1 = NEGINF, lr0 = 0.f, lr1 = 0.f;

    // ldmatrix lane addressing (element offsets within a tile)
    const int a_row = lane & 15;
    const int a_col = (lane >> 4) << 3;
    const int kb_r  = (lane & 7) + ((lane >> 4) << 3);
    const int kb_c  = ((lane >> 3) & 1) << 3;
    const int vb_r  = (lane & 7) + (((lane >> 3) & 1) << 3);
    const int vb_c  = (lane >> 4) << 3;
    const int r0    = lane >> 2;

    for (int kt = 0; kt < nk; ++kt) {
        const int k0 = kt * BN;
        const int s  = kt & 1;

        // ---- Prefetch tile kt+1 into the other stage ----
        if (kt + 1 < nk) {
            const int sn = (kt + 1) & 1;
            const size_t kvoff = ((size_t)(b * PS + (kt + 1) * BN) * PHKV + hk) * PD;
            const __nv_bfloat16* gsrc[4] = { g_khi + kvoff, g_klo + kvoff,
                                             g_vhi + kvoff, g_vlo + kvoff };
            #pragma unroll
            for (int a = 0; a < 4; ++a)
                #pragma unroll
                for (int it = 0; it < 4; ++it) {
                    int ci = tid + it * NT;
                    int r = ci >> 4, c = ci & 15;
                    cpa16(smb + (SM_ST(sn, a) + r * STR + c * 8) * 2,
                          gsrc[a] + (size_t)r * (PHKV * PD) + c * 8);
                }
            CP_COMMIT();
            CP_WAIT(1);      // tile kt complete; kt+1 may remain in flight
        } else {
            CP_WAIT(0);      // final tile complete
        }
        __syncthreads();     // cp.async data + (kt==0) Q stores visible to all

        // ---- S = Q @ K^T : 8 n-blocks of m16n8, 8 ksteps of 16 ----
        float sc[8][4];
        #pragma unroll
        for (int nb = 0; nb < 8; ++nb)
            #pragma unroll
            for (int j = 0; j < 4; ++j) sc[nb][j] = 0.f;

        #pragma unroll
        for (int ks = 0; ks < 8; ++ks) {
            const int kc = ks * 16;
            unsigned ah[4], al[4], bh[16], bl[16];
            ldsm4(ah, smb + (SM_QH + (m0 + a_row) * STR + kc + a_col) * 2);
            ldsm4(al, smb + (SM_QL + (m0 + a_row) * STR + kc + a_col) * 2);
            #pragma unroll
            for (int nbp = 0; nbp < 4; ++nbp) {
                ldsm4(&bh[nbp * 4], smb + (SM_ST(s, 0) + (nbp * 16 + kb_r) * STR + kc + kb_c) * 2);
                ldsm4(&bl[nbp * 4], smb + (SM_ST(s, 1) + (nbp * 16 + kb_r) * STR + kc + kb_c) * 2);
            }
            #pragma unroll
            for (int nb = 0; nb < 8; ++nb) mma_bf16(sc[nb], ah, &bh[nb * 2]);
            #pragma unroll
            for (int nb = 0; nb < 8; ++nb) mma_bf16(sc[nb], al, &bh[nb * 2]);
            #pragma unroll
            for (int nb = 0; nb < 8; ++nb) mma_bf16(sc[nb], ah, &bl[nb * 2]);
        }

        // ---- Causal mask (last two k-tiles of this q-tile) ----
        const int qr0 = q0 + m0 + r0;
        const int qr1 = qr0 + 8;
        if (kt >= nk - 2) {
            #pragma unroll
            for (int nb = 0; nb < 8; ++nb) {
                int n = k0 + nb * 8 + ((lane & 3) << 1);
                if (n     > qr0) sc[nb][0] = NEGINF;
                if (n + 1 > qr0) sc[nb][1] = NEGINF;
                if (n     > qr1) sc[nb][2] = NEGINF;
                if (n + 1 > qr1) sc[nb][3] = NEGINF;
            }
        }

        // ---- Online softmax (rows r0, r0+8; 4 threads/row via shfl) ----
        float mx0 = NEGINF, mx1 = NEGINF;
        #pragma unroll
        for (int nb = 0; nb < 8; ++nb) {
            mx0 = fmaxf(mx0, fmaxf(sc[nb][0], sc[nb][1]));
            mx1 = fmaxf(mx1, fmaxf(sc[nb][2], sc[nb][3]));
        }
        mx0 = fmaxf(mx0, __shfl_xor_sync(0xffffffffu, mx0, 1));
        mx0 = fmaxf(mx0, __shfl_xor_sync(0xffffffffu, mx0, 2));
        mx1 = fmaxf(mx1, __shfl_xor_sync(0xffffffffu, mx1, 1));
        mx1 = fmaxf(mx1, __shfl_xor_sync(0xffffffffu, mx1, 2));
        float mn0 = fmaxf(mr0, mx0), mn1 = fmaxf(mr1, mx1);
        float al0 = __expf(mr0 - mn0), al1 = __expf(mr1 - mn1);
        float s0 = 0.f, s1 = 0.f;
        #pragma unroll
        for (int nb = 0; nb < 8; ++nb) {
            sc[nb][0] = __expf(sc[nb][0] - mn0); s0 += sc[nb][0];
            sc[nb][1] = __expf(sc[nb][1] - mn0); s0 += sc[nb][1];
            sc[nb][2] = __expf(sc[nb][2] - mn1); s1 += sc[nb][2];
            sc[nb][3] = __expf(sc[nb][3] - mn1); s1 += sc[nb][3];
        }
        s0 += __shfl_xor_sync(0xffffffffu, s0, 1);
        s0 += __shfl_xor_sync(0xffffffffu, s0, 2);
        s1 += __shfl_xor_sync(0xffffffffu, s1, 1);
        s1 += __shfl_xor_sync(0xffffffffu, s1, 2);
        lr0 = lr0 * al0 + s0; lr1 = lr1 * al1 + s1;
        mr0 = mn0; mr1 = mn1;
        #pragma unroll
        for (int nb = 0; nb < 16; ++nb) {
            oc[nb][0] *= al0; oc[nb][1] *= al0;
            oc[nb][2] *= al1; oc[nb][3] *= al1;
        }

        // ---- O += P @ V : P in regs (C-frag -> A-frag), V via ldmatrix.trans ----
        #pragma unroll
        for (int kk = 0; kk < 4; ++kk) {
            unsigned pah[4], pal[4];
            split2(sc[2 * kk][0],     sc[2 * kk][1],     pah[0], pal[0]);
            split2(sc[2 * kk][2],     sc[2 * kk][3],     pah[1], pal[1]);
            split2(sc[2 * kk + 1][0], sc[2 * kk + 1][1], pah[2], pal[2]);
            split2(sc[2 * kk + 1][2], sc[2 * kk + 1][3], pah[3], pal[3]);
            #pragma unroll
            for (int half = 0; half < 2; ++half) {
                unsigned bh[16], bl[16];
                #pragma unroll
                for (int nbp = 0; nbp < 4; ++nbp) {
                    int ncol = half * 64 + nbp * 16 + vb_c;
                    ldsm4t(&bh[nbp * 4], smb + (SM_ST(s, 2) + (kk * 16 + vb_r) * STR + ncol) * 2);
                    ldsm4t(&bl[nbp * 4], smb + (SM_ST(s, 3) + (kk * 16 + vb_r) * STR + ncol) * 2);
                }
                #pragma unroll
                for (int j = 0; j < 8; ++j) mma_bf16(oc[half * 8 + j], pah, &bh[j * 2]);
                #pragma unroll
                for (int j = 0; j < 8; ++j) mma_bf16(oc[half * 8 + j], pal, &bh[j * 2]);
                #pragma unroll
                for (int j = 0; j < 8; ++j) mma_bf16(oc[half * 8 + j], pah, &bl[j * 2]);
            }
        }
        __syncthreads();     // all warps done reading stage s before it is refilled
    }

    // ---- Epilogue: O / l ----
    {
        const float inv0 = 1.f / lr0, inv1 = 1.f / lr1;
        const int qrA = q0 + m0 + r0;
        const int qrB = qrA + 8;
        float* oA = out + ((size_t)(b * PS + qrA) * PHQ + h) * PD;
        float* oB = out + ((size_t)(b * PS + qrB) * PHQ + h) * PD;
        #pragma unroll
        for (int nb = 0; nb < 16; ++nb) {
            int n = nb * 8 + ((lane & 3) << 1);
            *(float2*)(oA + n) = make_float2(oc[nb][0] * inv0, oc[nb][1] * inv0);
            *(float2*)(oB + n) = make_float2(oc[nb][2] * inv1, oc[nb][3] * inv1);
        }
    }
}

// ---------------------------------------------------------------------------
// KV-cache scatter: kv_out[sel[i]] = concat(xk_row_i, xv_row_i)
// ---------------------------------------------------------------------------
__global__ void kv_scatter_kernel(const float* __restrict__ xk,
                                  const float* __restrict__ xv,
                                  const int* __restrict__ sel,
                                  float* __restrict__ kv_out)
{
    int idx = blockIdx.x * blockDim.x + threadIdx.x;   // over (B*S)*512 float4
    int row = idx >> 9;
    int w   = idx & 511;
    if (row >= PB * PS) return;
    int dst = sel[row];
    float4 v;
    if (w < 256) {
        v = ((const float4*)xk)[row * 256 + w];
    } else {
        v = ((const float4*)xv)[row * 256 + (w - 256)];
    }
    ((float4*)kv_out)[(size_t)dst * 512 + w] = v;
}

// ---------------------------------------------------------------------------
extern "C" void kernel_launch(void* const* d_in, const int* in_sizes, int n_in,
                              void* d_out, int out_size)
{
    const float* xq    = (const float*)d_in[0];
    const float* xk    = (const float*)d_in[1];
    const float* xv    = (const float*)d_in[2];
    const float* kvbuf = (const float*)d_in[3];
    const int*   sel   = (const int*)d_in[4];
    float* out = (float*)d_out;

    const size_t attn_elems = (size_t)PB * PS * PHQ * PD;          // 8388608
    const size_t kv_elems   = (size_t)PB * PS * 2 * PHKV * PD;     // 4194304

    cudaFuncSetAttribute(attn_kernel,
                         cudaFuncAttributeMaxDynamicSharedMemorySize,
                         SMEM_BYTES);

    // 1) pre-split K/V to bf16 hi/lo scratch
    split_kv_kernel<<<(2 * 524288) / 256, 256>>>(xk, xv);

    // 2) attention
    dim3 grid(PS / BM, PHQ, PB);
    attn_kernel<<<grid, NT, SMEM_BYTES>>>(xq, out);

    // 3) kv-cache output
    if ((size_t)out_size >= attn_elems + kv_elems) {
        float* kv_out = out + attn_elems;
        cudaMemcpyAsync(kv_out, kvbuf, kv_elems * sizeof(float),
                        cudaMemcpyDeviceToDevice);
        int total4 = PB * PS * 512;
        kv_scatter_kernel<<<(total4 + 255) / 256, 256>>>(xk, xv, sel, kv_out);
    }
}

// round 10
// speedup vs baseline: 1.2128x; 1.2128x over previous
#include <cuda_runtime.h>
#include <cuda_bf16.h>

// Problem constants
#define PB   2
#define PS   1024
#define PHQ  32
#define PHKV 8
#define PG   (PHQ / PHKV)   // 4
#define PD   128

#define BM 64
#define BN 64
#define NT 128              // 4 warps; each warp owns a 16-row stripe

// scale folded with log2(e): softmax computed in base-2 domain
#define SCALE (0.08838834764831845f * 1.4426950408889634f)
#define NEGINF (-1e30f)

#define STR 136             // bf16 smem row stride (128 + 8 pad) -> conflict-free ldmatrix

// smem offsets in bf16 elements
#define SM_QH 0
#define SM_QL (SM_QH + BM * STR)
#define SM_KH (SM_QL + BM * STR)
#define SM_KL (SM_KH + BN * STR)
#define SM_VH (SM_KL + BN * STR)
#define SM_VL (SM_VH + BN * STR)
#define SM_TOT (SM_VL + BN * STR)        // 52224 bf16
#define SMEM_BYTES (SM_TOT * 2)          // 104448 bytes -> 2 CTAs/SM

// Pre-split K/V scratch (bf16 hi/lo), layout [b, s, hkv, d]
#define KV_ELEMS (PB * PS * PHKV * PD)   // 2097152
__device__ __nv_bfloat16 g_khi[KV_ELEMS];
__device__ __nv_bfloat16 g_klo[KV_ELEMS];
__device__ __nv_bfloat16 g_vhi[KV_ELEMS];
__device__ __nv_bfloat16 g_vlo[KV_ELEMS];

// ---------------------------------------------------------------------------
// PTX helpers
// ---------------------------------------------------------------------------
__device__ __forceinline__ void ldsm4(unsigned* r, unsigned addr) {
    asm volatile("ldmatrix.sync.aligned.m8n8.x4.shared.b16 {%0,%1,%2,%3}, [%4];"
                 : "=r"(r[0]), "=r"(r[1]), "=r"(r[2]), "=r"(r[3]) : "r"(addr));
}
__device__ __forceinline__ void ldsm4t(unsigned* r, unsigned addr) {
    asm volatile("ldmatrix.sync.aligned.m8n8.x4.trans.shared.b16 {%0,%1,%2,%3}, [%4];"
                 : "=r"(r[0]), "=r"(r[1]), "=r"(r[2]), "=r"(r[3]) : "r"(addr));
}
__device__ __forceinline__ void mma_bf16(float* c, const unsigned* a, const unsigned* b) {
    asm volatile(
        "mma.sync.aligned.m16n8k16.row.col.f32.bf16.bf16.f32 "
        "{%0,%1,%2,%3}, {%4,%5,%6,%7}, {%8,%9}, {%0,%1,%2,%3};"
        : "+f"(c[0]), "+f"(c[1]), "+f"(c[2]), "+f"(c[3])
        : "r"(a[0]), "r"(a[1]), "r"(a[2]), "r"(a[3]), "r"(b[0]), "r"(b[1]));
}
__device__ __forceinline__ void cpa16(unsigned dst, const void* src) {
    asm volatile("cp.async.cg.shared.global [%0], [%1], 16;" :: "r"(dst), "l"(src));
}
#define CP_COMMIT()  asm volatile("cp.async.commit_group;" ::: "memory")
#define CP_WAIT(N)   asm volatile("cp.async.wait_group %0;" :: "n"(N) : "memory")

// Split fp32 pair into (hi, lo) bf16x2 packed registers: x = hi + lo
__device__ __forceinline__ void split2(float x0, float x1, unsigned& hi, unsigned& lo) {
    __nv_bfloat16 h0 = __float2bfloat16(x0);
    __nv_bfloat16 h1 = __float2bfloat16(x1);
    float r0 = x0 - __bfloat162float(h0);
    float r1 = x1 - __bfloat162float(h1);
    __nv_bfloat162 H(h0, h1);
    __nv_bfloat162 L(__float2bfloat16(r0), __float2bfloat16(r1));
    hi = *reinterpret_cast<unsigned*>(&H);
    lo = *reinterpret_cast<unsigned*>(&L);
}

// ---------------------------------------------------------------------------
// Fused: KV-cache scatter (kv_out[sel[i]] = concat(k_i, v_i)) + bf16 hi/lo
// pre-split of K and V into scratch for the attention mainloop.
// One pass over xk/xv. Grid covers (B*S) rows x 512 float4 per row.
// ---------------------------------------------------------------------------
__global__ void kv_scatter_split_kernel(const float* __restrict__ xk,
                                        const float* __restrict__ xv,
                                        const int* __restrict__ sel,
                                        float* __restrict__ kv_out)
{
    int idx = blockIdx.x * blockDim.x + threadIdx.x;
    int row = idx >> 9;
    int w   = idx & 511;
    if (row >= PB * PS) return;
    int dst = sel[row];
    float4 v;
    __nv_bfloat16 *hi, *lo;
    int e;
    if (w < 256) {
        v = ((const float4*)xk)[row * 256 + w];
        hi = g_khi; lo = g_klo; e = row * 1024 + w * 4;
    } else {
        v = ((const float4*)xv)[row * 256 + (w - 256)];
        hi = g_vhi; lo = g_vlo; e = row * 1024 + (w - 256) * 4;
    }
    ((float4*)kv_out)[(size_t)dst * 512 + w] = v;
    unsigned h01, l01, h23, l23;
    split2(v.x, v.y, h01, l01);
    split2(v.z, v.w, h23, l23);
    *(unsigned*)(hi + e)     = h01;
    *(unsigned*)(hi + e + 2) = h23;
    *(unsigned*)(lo + e)     = l01;
    *(unsigned*)(lo + e + 2) = l23;
}

// ---------------------------------------------------------------------------
// Flash attention, tensor-core path (split-bf16, 3-term), cp.async K/V loads
// from pre-split scratch. One CTA per (q-tile=64, head, batch). 4 warps.
// S tile kept in registers (QK C-frag == PV A-frag layout). 2 CTAs/SM.
// ---------------------------------------------------------------------------
__global__ __launch_bounds__(NT)
void attn_kernel(const float* __restrict__ xq, float* __restrict__ out)
{
    extern __shared__ __nv_bfloat16 sm[];
    const unsigned smb = (unsigned)__cvta_generic_to_shared(sm);

    const int qt = blockIdx.x;
    const int h  = blockIdx.y;
    const int b  = blockIdx.z;
    const int hk = h / PG;
    const int tid  = threadIdx.x;
    const int lane = tid & 31;
    const int wid  = tid >> 5;
    const int q0 = qt * BM;
    const int m0 = wid * 16;

    // ---- Load + split Q tile (pre-scaled, incl. log2e) into smem ----
    {
        const float* qbase = xq + ((size_t)(b * PS + q0) * PHQ + h) * PD;
        #pragma unroll
        for (int it = 0; it < (BM * PD / 4) / NT; ++it) {   // 16 iters
            int idx = tid + it * NT;
            int r = idx >> 5;
            int c4 = idx & 31;
            float4 v = *(const float4*)(qbase + (size_t)r * (PHQ * PD) + c4 * 4);
            v.x *= SCALE; v.y *= SCALE; v.z *= SCALE; v.w *= SCALE;
            unsigned h01, l01, h23, l23;
            split2(v.x, v.y, h01, l01);
            split2(v.z, v.w, h23, l23);
            int o = r * STR + c4 * 4;
            *(unsigned*)(sm + SM_QH + o)     = h01;
            *(unsigned*)(sm + SM_QH + o + 2) = h23;
            *(unsigned*)(sm + SM_QL + o)     = l01;
            *(unsigned*)(sm + SM_QL + o + 2) = l23;
        }
    }

    // Output accumulators: 16 n-blocks of m16n8 C-frags
    float oc[16][4];
    #pragma unroll
    for (int nb = 0; nb < 16; ++nb)
        #pragma unroll
        for (int j = 0; j < 4; ++j) oc[nb][j] = 0.f;
    float mr0 = NEGINF, mr1 = NEGINF, lr0 = 0.f, lr1 = 0.f;

    // ldmatrix lane addressing (element offsets within a tile)
    const int a_row = lane & 15;
    const int a_col = (lane >> 4) << 3;
    const int kb_r  = (lane & 7) + ((lane >> 4) << 3);
    const int kb_c  = ((lane >> 3) & 1) << 3;
    const int vb_r  = (lane & 7) + (((lane >> 3) & 1) << 3);
    const int vb_c  = (lane >> 4) << 3;
    const int r0    = lane >> 2;

    for (int kt = 0; kt <= qt; ++kt) {
        const int k0 = kt * BN;
        __syncthreads();   // all warps done reading prev tile's K/V smem

        // ---- Issue cp.async: group A = K(hi,lo), group B = V(hi,lo) ----
        {
            const size_t kvoff = ((size_t)(b * PS + k0) * PHKV + hk) * PD;
            #pragma unroll
            for (int it = 0; it < 8; ++it) {
                int ci = tid + it * NT;       // 0..1023 (64 rows x 16 chunks)
                int r = ci >> 4, c = ci & 15;
                cpa16(smb + (SM_KH + r * STR + c * 8) * 2,
                      g_khi + kvoff + (size_t)r * (PHKV * PD) + c * 8);
                cpa16(smb + (SM_KL + r * STR + c * 8) * 2,
                      g_klo + kvoff + (size_t)r * (PHKV * PD) + c * 8);
            }
            CP_COMMIT();
            #pragma unroll
            for (int it = 0; it < 8; ++it) {
                int ci = tid + it * NT;
                int r = ci >> 4, c = ci & 15;
                cpa16(smb + (SM_VH + r * STR + c * 8) * 2,
                      g_vhi + kvoff + (size_t)r * (PHKV * PD) + c * 8);
                cpa16(smb + (SM_VL + r * STR + c * 8) * 2,
                      g_vlo + kvoff + (size_t)r * (PHKV * PD) + c * 8);
            }
            CP_COMMIT();
        }
        CP_WAIT(1);          // K complete; V may still be in flight
        __syncthreads();

        // ---- S = Q @ K^T : 8 n-blocks of m16n8, 8 ksteps of 16 ----
        float sc[8][4];
        #pragma unroll
        for (int nb = 0; nb < 8; ++nb)
            #pragma unroll
            for (int j = 0; j < 4; ++j) sc[nb][j] = 0.f;

        #pragma unroll
        for (int ks = 0; ks < 8; ++ks) {
            const int kc = ks * 16;
            unsigned ah[4], al[4], bh[16], bl[16];
            ldsm4(ah, smb + (SM_QH + (m0 + a_row) * STR + kc + a_col) * 2);
            ldsm4(al, smb + (SM_QL + (m0 + a_row) * STR + kc + a_col) * 2);
            #pragma unroll
            for (int nbp = 0; nbp < 4; ++nbp) {
                ldsm4(&bh[nbp * 4], smb + (SM_KH + (nbp * 16 + kb_r) * STR + kc + kb_c) * 2);
                ldsm4(&bl[nbp * 4], smb + (SM_KL + (nbp * 16 + kb_r) * STR + kc + kb_c) * 2);
            }
            #pragma unroll
            for (int nb = 0; nb < 8; ++nb) mma_bf16(sc[nb], ah, &bh[nb * 2]);
            #pragma unroll
            for (int nb = 0; nb < 8; ++nb) mma_bf16(sc[nb], al, &bh[nb * 2]);
            #pragma unroll
            for (int nb = 0; nb < 8; ++nb) mma_bf16(sc[nb], ah, &bl[nb * 2]);
        }

        // ---- Causal mask (diagonal tile only) ----
        const int qr0 = q0 + m0 + r0;
        const int qr1 = qr0 + 8;
        if (kt == qt) {
            #pragma unroll
            for (int nb = 0; nb < 8; ++nb) {
                int n = k0 + nb * 8 + ((lane & 3) << 1);
                if (n     > qr0) sc[nb][0] = NEGINF;
                if (n + 1 > qr0) sc[nb][1] = NEGINF;
                if (n     > qr1) sc[nb][2] = NEGINF;
                if (n + 1 > qr1) sc[nb][3] = NEGINF;
            }
        }

        // ---- Online softmax in base-2 (rows r0, r0+8; 4 threads/row) ----
        float mx0 = NEGINF, mx1 = NEGINF;
        #pragma unroll
        for (int nb = 0; nb < 8; ++nb) {
            mx0 = fmaxf(mx0, fmaxf(sc[nb][0], sc[nb][1]));
            mx1 = fmaxf(mx1, fmaxf(sc[nb][2], sc[nb][3]));
        }
        mx0 = fmaxf(mx0, __shfl_xor_sync(0xffffffffu, mx0, 1));
        mx0 = fmaxf(mx0, __shfl_xor_sync(0xffffffffu, mx0, 2));
        mx1 = fmaxf(mx1, __shfl_xor_sync(0xffffffffu, mx1, 1));
        mx1 = fmaxf(mx1, __shfl_xor_sync(0xffffffffu, mx1, 2));
        float mn0 = fmaxf(mr0, mx0), mn1 = fmaxf(mr1, mx1);
        float al0 = exp2f(mr0 - mn0), al1 = exp2f(mr1 - mn1);
        float s0 = 0.f, s1 = 0.f;
        #pragma unroll
        for (int nb = 0; nb < 8; ++nb) {
            sc[nb][0] = exp2f(sc[nb][0] - mn0); s0 += sc[nb][0];
            sc[nb][1] = exp2f(sc[nb][1] - mn0); s0 += sc[nb][1];
            sc[nb][2] = exp2f(sc[nb][2] - mn1); s1 += sc[nb][2];
            sc[nb][3] = exp2f(sc[nb][3] - mn1); s1 += sc[nb][3];
        }
        s0 += __shfl_xor_sync(0xffffffffu, s0, 1);
        s0 += __shfl_xor_sync(0xffffffffu, s0, 2);
        s1 += __shfl_xor_sync(0xffffffffu, s1, 1);
        s1 += __shfl_xor_sync(0xffffffffu, s1, 2);
        lr0 = lr0 * al0 + s0; lr1 = lr1 * al1 + s1;
        mr0 = mn0; mr1 = mn1;
        #pragma unroll
        for (int nb = 0; nb < 16; ++nb) {
            oc[nb][0] *= al0; oc[nb][1] *= al0;
            oc[nb][2] *= al1; oc[nb][3] *= al1;
        }

        CP_WAIT(0);          // V complete (overlapped with QK+softmax)
        __syncthreads();

        // ---- O += P @ V : P in regs (C-frag -> A-frag), V via ldmatrix.trans ----
        #pragma unroll
        for (int kk = 0; kk < 4; ++kk) {
            unsigned pah[4], pal[4];
            split2(sc[2 * kk][0],     sc[2 * kk][1],     pah[0], pal[0]);
            split2(sc[2 * kk][2],     sc[2 * kk][3],     pah[1], pal[1]);
            split2(sc[2 * kk + 1][0], sc[2 * kk + 1][1], pah[2], pal[2]);
            split2(sc[2 * kk + 1][2], sc[2 * kk + 1][3], pah[3], pal[3]);
            #pragma unroll
            for (int half = 0; half < 2; ++half) {
                unsigned bh[16], bl[16];
                #pragma unroll
                for (int nbp = 0; nbp < 4; ++nbp) {
                    int ncol = half * 64 + nbp * 16 + vb_c;
                    ldsm4t(&bh[nbp * 4], smb + (SM_VH + (kk * 16 + vb_r) * STR + ncol) * 2);
                    ldsm4t(&bl[nbp * 4], smb + (SM_VL + (kk * 16 + vb_r) * STR + ncol) * 2);
                }
                #pragma unroll
                for (int j = 0; j < 8; ++j) mma_bf16(oc[half * 8 + j], pah, &bh[j * 2]);
                #pragma unroll
                for (int j = 0; j < 8; ++j) mma_bf16(oc[half * 8 + j], pal, &bh[j * 2]);
                #pragma unroll
                for (int j = 0; j < 8; ++j) mma_bf16(oc[half * 8 + j], pah, &bl[j * 2]);
            }
        }
    }

    // ---- Epilogue: O / l ----
    {
        const float inv0 = 1.f / lr0, inv1 = 1.f / lr1;
        const int qrA = q0 + m0 + r0;
        const int qrB = qrA + 8;
        float* oA = out + ((size_t)(b * PS + qrA) * PHQ + h) * PD;
        float* oB = out + ((size_t)(b * PS + qrB) * PHQ + h) * PD;
        #pragma unroll
        for (int nb = 0; nb < 16; ++nb) {
            int n = nb * 8 + ((lane & 3) << 1);
            *(float2*)(oA + n) = make_float2(oc[nb][0] * inv0, oc[nb][1] * inv0);
            *(float2*)(oB + n) = make_float2(oc[nb][2] * inv1, oc[nb][3] * inv1);
        }
    }
}

// ---------------------------------------------------------------------------
extern "C" void kernel_launch(void* const* d_in, const int* in_sizes, int n_in,
                              void* d_out, int out_size)
{
    const float* xq    = (const float*)d_in[0];
    const float* xk    = (const float*)d_in[1];
    const float* xv    = (const float*)d_in[2];
    const float* kvbuf = (const float*)d_in[3];
    const int*   sel   = (const int*)d_in[4];
    float* out = (float*)d_out;

    const size_t attn_elems = (size_t)PB * PS * PHQ * PD;          // 8388608
    const size_t kv_elems   = (size_t)PB * PS * 2 * PHKV * PD;     // 4194304

    cudaFuncSetAttribute(attn_kernel,
                         cudaFuncAttributeMaxDynamicSharedMemorySize,
                         SMEM_BYTES);

    // 1) kv-cache base copy (covers rows not hit by the scatter)
    float* kv_out = out + attn_elems;
    cudaMemcpyAsync(kv_out, kvbuf, kv_elems * sizeof(float),
                    cudaMemcpyDeviceToDevice);

    // 2) fused scatter + bf16 hi/lo pre-split (one pass over xk/xv)
    {
        int total4 = PB * PS * 512;
        kv_scatter_split_kernel<<<(total4 + 255) / 256, 256>>>(xk, xv, sel, kv_out);
    }

    // 3) attention (consumes the pre-split scratch)
    dim3 grid(PS / BM, PHQ, PB);
    attn_kernel<<<grid, NT, SMEM_BYTES>>>(xq, out);
}

// round 13
// speedup vs baseline: 2.4421x; 2.0136x over previous
#include <cuda_runtime.h>
#include <cuda_fp16.h>

// Problem constants
#define PB   2
#define PS   1024
#define PHQ  32
#define PHKV 8
#define PG   (PHQ / PHKV)   // 4
#define PD   128

#define BM 64
#define BN 64
#define NT 128              // 4 warps; each warp owns a 16-row stripe

// scale folded with log2(e): softmax computed in base-2 domain
#define SCALE (0.08838834764831845f * 1.4426950408889634f)
#define NEGINF (-1e30f)

#define STR 136             // fp16 smem row stride (128 + 8 pad) -> conflict-free ldmatrix

// smem offsets in fp16 elements
#define SM_Q  0
#define SM_K  (SM_Q + BM * STR)
#define SM_V  (SM_K + BN * STR)
#define SM_TOT (SM_V + BN * STR)         // 3 * 8704 = 26112 halfs
#define SMEM_BYTES (SM_TOT * 2)          // 52224 bytes -> 3+ CTAs/SM

// Pre-converted K/V scratch (fp16), layout [b, s, hkv, d]
#define KV_ELEMS (PB * PS * PHKV * PD)   // 2097152
__device__ __half g_kh[KV_ELEMS];
__device__ __half g_vh[KV_ELEMS];

// ---------------------------------------------------------------------------
// PTX helpers
// ---------------------------------------------------------------------------
__device__ __forceinline__ void ldsm4(unsigned* r, unsigned addr) {
    asm volatile("ldmatrix.sync.aligned.m8n8.x4.shared.b16 {%0,%1,%2,%3}, [%4];"
                 : "=r"(r[0]), "=r"(r[1]), "=r"(r[2]), "=r"(r[3]) : "r"(addr));
}
__device__ __forceinline__ void ldsm4t(unsigned* r, unsigned addr) {
    asm volatile("ldmatrix.sync.aligned.m8n8.x4.trans.shared.b16 {%0,%1,%2,%3}, [%4];"
                 : "=r"(r[0]), "=r"(r[1]), "=r"(r[2]), "=r"(r[3]) : "r"(addr));
}
__device__ __forceinline__ void mma_f16(float* c, const unsigned* a, const unsigned* b) {
    asm volatile(
        "mma.sync.aligned.m16n8k16.row.col.f32.f16.f16.f32 "
        "{%0,%1,%2,%3}, {%4,%5,%6,%7}, {%8,%9}, {%0,%1,%2,%3};"
        : "+f"(c[0]), "+f"(c[1]), "+f"(c[2]), "+f"(c[3])
        : "r"(a[0]), "r"(a[1]), "r"(a[2]), "r"(a[3]), "r"(b[0]), "r"(b[1]));
}
__device__ __forceinline__ void cpa16(unsigned dst, const void* src) {
    asm volatile("cp.async.cg.shared.global [%0], [%1], 16;" :: "r"(dst), "l"(src));
}
#define CP_COMMIT()  asm volatile("cp.async.commit_group;" ::: "memory")
#define CP_WAIT(N)   asm volatile("cp.async.wait_group %0;" :: "n"(N) : "memory")

// Pack two fp32 into one fp16x2 register
__device__ __forceinline__ unsigned pack2h(float x0, float x1) {
    __half2 h = __floats2half2_rn(x0, x1);
    return *reinterpret_cast<unsigned*>(&h);
}

// ---------------------------------------------------------------------------
// Fused: KV-cache scatter (kv_out[sel[i]] = concat(k_i, v_i)) + fp16 convert
// of K and V into scratch for the attention mainloop. One pass over xk/xv.
// Grid covers (B*S) rows x 512 float4 per row.
// ---------------------------------------------------------------------------
__global__ void kv_scatter_h_kernel(const float* __restrict__ xk,
                                    const float* __restrict__ xv,
                                    const int* __restrict__ sel,
                                    float* __restrict__ kv_out)
{
    int idx = blockIdx.x * blockDim.x + threadIdx.x;
    int row = idx >> 9;
    int w   = idx & 511;
    if (row >= PB * PS) return;
    int dst = sel[row];
    float4 v;
    __half* gh;
    int e;
    if (w < 256) {
        v = ((const float4*)xk)[row * 256 + w];
        gh = g_kh; e = row * 1024 + w * 4;
    } else {
        v = ((const float4*)xv)[row * 256 + (w - 256)];
        gh = g_vh; e = row * 1024 + (w - 256) * 4;
    }
    ((float4*)kv_out)[(size_t)dst * 512 + w] = v;
    *(unsigned*)(gh + e)     = pack2h(v.x, v.y);
    *(unsigned*)(gh + e + 2) = pack2h(v.z, v.w);
}

// ---------------------------------------------------------------------------
// Flash attention, fp16 tensor-core path (single-term, fp32 accumulate).
// cp.async K/V loads from fp16 scratch. One CTA per (q-tile=64, head, batch).
// 4 warps; warp w owns rows [16w, 16w+16). S kept in registers. 3 CTAs/SM.
// ---------------------------------------------------------------------------
__global__ __launch_bounds__(NT, 3)
void attn_kernel(const float* __restrict__ xq, float* __restrict__ out)
{
    extern __shared__ __half sm[];
    const unsigned smb = (unsigned)__cvta_generic_to_shared(sm);

    const int qt = blockIdx.x;
    const int h  = blockIdx.y;
    const int b  = blockIdx.z;
    const int hk = h / PG;
    const int tid  = threadIdx.x;
    const int lane = tid & 31;
    const int wid  = tid >> 5;
    const int q0 = qt * BM;
    const int m0 = wid * 16;

    // ---- Load Q tile (pre-scaled incl. log2e) into fp16 smem ----
    {
        const float* qbase = xq + ((size_t)(b * PS + q0) * PHQ + h) * PD;
        #pragma unroll
        for (int it = 0; it < (BM * PD / 4) / NT; ++it) {   // 16 iters
            int idx = tid + it * NT;
            int r = idx >> 5;
            int c4 = idx & 31;
            float4 v = *(const float4*)(qbase + (size_t)r * (PHQ * PD) + c4 * 4);
            v.x *= SCALE; v.y *= SCALE; v.z *= SCALE; v.w *= SCALE;
            int o = r * STR + c4 * 4;
            *(unsigned*)(sm + SM_Q + o)     = pack2h(v.x, v.y);
            *(unsigned*)(sm + SM_Q + o + 2) = pack2h(v.z, v.w);
        }
    }

    // Output accumulators: 16 n-blocks of m16n8 C-frags
    float oc[16][4];
    #pragma unroll
    for (int nb = 0; nb < 16; ++nb)
        #pragma unroll
        for (int j = 0; j < 4; ++j) oc[nb][j] = 0.f;
    float mr0 = NEGINF, mr1 = NEGINF, lr0 = 0.f, lr1 = 0.f;

    // ldmatrix lane addressing (element offsets within a tile)
    const int a_row = lane & 15;
    const int a_col = (lane >> 4) << 3;
    const int kb_r  = (lane & 7) + ((lane >> 4) << 3);
    const int kb_c  = ((lane >> 3) & 1) << 3;
    const int vb_r  = (lane & 7) + (((lane >> 3) & 1) << 3);
    const int vb_c  = (lane >> 4) << 3;
    const int r0    = lane >> 2;

    for (int kt = 0; kt <= qt; ++kt) {
        const int k0 = kt * BN;
        __syncthreads();   // all warps done reading prev tile's K/V smem

        // ---- Issue cp.async: group A = K, group B = V ----
        {
            const size_t kvoff = ((size_t)(b * PS + k0) * PHKV + hk) * PD;
            #pragma unroll
            for (int it = 0; it < 8; ++it) {
                int ci = tid + it * NT;       // 0..1023 (64 rows x 16 chunks)
                int r = ci >> 4, c = ci & 15;
                cpa16(smb + (SM_K + r * STR + c * 8) * 2,
                      g_kh + kvoff + (size_t)r * (PHKV * PD) + c * 8);
            }
            CP_COMMIT();
            #pragma unroll
            for (int it = 0; it < 8; ++it) {
                int ci = tid + it * NT;
                int r = ci >> 4, c = ci & 15;
                cpa16(smb + (SM_V + r * STR + c * 8) * 2,
                      g_vh + kvoff + (size_t)r * (PHKV * PD) + c * 8);
            }
            CP_COMMIT();
        }
        CP_WAIT(1);          // K complete; V may still be in flight
        __syncthreads();

        // ---- S = Q @ K^T : 8 n-blocks of m16n8, 8 ksteps of 16 ----
        float sc[8][4];
        #pragma unroll
        for (int nb = 0; nb < 8; ++nb)
            #pragma unroll
            for (int j = 0; j < 4; ++j) sc[nb][j] = 0.f;

        #pragma unroll
        for (int ks = 0; ks < 8; ++ks) {
            const int kc = ks * 16;
            unsigned ah[4], bh[16];
            ldsm4(ah, smb + (SM_Q + (m0 + a_row) * STR + kc + a_col) * 2);
            #pragma unroll
            for (int nbp = 0; nbp < 4; ++nbp)
                ldsm4(&bh[nbp * 4], smb + (SM_K + (nbp * 16 + kb_r) * STR + kc + kb_c) * 2);
            #pragma unroll
            for (int nb = 0; nb < 8; ++nb) mma_f16(sc[nb], ah, &bh[nb * 2]);
        }

        // ---- Causal mask (diagonal tile only) ----
        const int qr0 = q0 + m0 + r0;
        const int qr1 = qr0 + 8;
        if (kt == qt) {
            #pragma unroll
            for (int nb = 0; nb < 8; ++nb) {
                int n = k0 + nb * 8 + ((lane & 3) << 1);
                if (n     > qr0) sc[nb][0] = NEGINF;
                if (n + 1 > qr0) sc[nb][1] = NEGINF;
                if (n     > qr1) sc[nb][2] = NEGINF;
                if (n + 1 > qr1) sc[nb][3] = NEGINF;
            }
        }

        // ---- Online softmax in base-2 (rows r0, r0+8; 4 threads/row) ----
        float mx0 = NEGINF, mx1 = NEGINF;
        #pragma unroll
        for (int nb = 0; nb < 8; ++nb) {
            mx0 = fmaxf(mx0, fmaxf(sc[nb][0], sc[nb][1]));
            mx1 = fmaxf(mx1, fmaxf(sc[nb][2], sc[nb][3]));
        }
        mx0 = fmaxf(mx0, __shfl_xor_sync(0xffffffffu, mx0, 1));
        mx0 = fmaxf(mx0, __shfl_xor_sync(0xffffffffu, mx0, 2));
        mx1 = fmaxf(mx1, __shfl_xor_sync(0xffffffffu, mx1, 1));
        mx1 = fmaxf(mx1, __shfl_xor_sync(0xffffffffu, mx1, 2));
        float mn0 = fmaxf(mr0, mx0), mn1 = fmaxf(mr1, mx1);
        float al0 = exp2f(mr0 - mn0), al1 = exp2f(mr1 - mn1);
        float s0 = 0.f, s1 = 0.f;
        #pragma unroll
        for (int nb = 0; nb < 8; ++nb) {
            sc[nb][0] = exp2f(sc[nb][0] - mn0); s0 += sc[nb][0];
            sc[nb][1] = exp2f(sc[nb][1] - mn0); s0 += sc[nb][1];
            sc[nb][2] = exp2f(sc[nb][2] - mn1); s1 += sc[nb][2];
            sc[nb][3] = exp2f(sc[nb][3] - mn1); s1 += sc[nb][3];
        }
        s0 += __shfl_xor_sync(0xffffffffu, s0, 1);
        s0 += __shfl_xor_sync(0xffffffffu, s0, 2);
        s1 += __shfl_xor_sync(0xffffffffu, s1, 1);
        s1 += __shfl_xor_sync(0xffffffffu, s1, 2);
        lr0 = lr0 * al0 + s0; lr1 = lr1 * al1 + s1;
        mr0 = mn0; mr1 = mn1;
        #pragma unroll
        for (int nb = 0; nb < 16; ++nb) {
            oc[nb][0] *= al0; oc[nb][1] *= al0;
            oc[nb][2] *= al1; oc[nb][3] *= al1;
        }

        CP_WAIT(0);          // V complete (overlapped with QK+softmax)
        __syncthreads();

        // ---- O += P @ V : P in regs (fp16 pack), V via ldmatrix.trans ----
        #pragma unroll
        for (int kk = 0; kk < 4; ++kk) {
            unsigned pa[4];
            pa[0] = pack2h(sc[2 * kk][0],     sc[2 * kk][1]);
            pa[1] = pack2h(sc[2 * kk][2],     sc[2 * kk][3]);
            pa[2] = pack2h(sc[2 * kk + 1][0], sc[2 * kk + 1][1]);
            pa[3] = pack2h(sc[2 * kk + 1][2], sc[2 * kk + 1][3]);
            #pragma unroll
            for (int half_ = 0; half_ < 2; ++half_) {
                unsigned bh[16];
                #pragma unroll
                for (int nbp = 0; nbp < 4; ++nbp) {
                    int ncol = half_ * 64 + nbp * 16 + vb_c;
                    ldsm4t(&bh[nbp * 4], smb + (SM_V + (kk * 16 + vb_r) * STR + ncol) * 2);
                }
                #pragma unroll
                for (int j = 0; j < 8; ++j) mma_f16(oc[half_ * 8 + j], pa, &bh[j * 2]);
            }
        }
    }

    // ---- Epilogue: O / l ----
    {
        const float inv0 = 1.f / lr0, inv1 = 1.f / lr1;
        const int qrA = q0 + m0 + r0;
        const int qrB = qrA + 8;
        float* oA = out + ((size_t)(b * PS + qrA) * PHQ + h) * PD;
        float* oB = out + ((size_t)(b * PS + qrB) * PHQ + h) * PD;
        #pragma unroll
        for (int nb = 0; nb < 16; ++nb) {
            int n = nb * 8 + ((lane & 3) << 1);
            *(float2*)(oA + n) = make_float2(oc[nb][0] * inv0, oc[nb][1] * inv0);
            *(float2*)(oB + n) = make_float2(oc[nb][2] * inv1, oc[nb][3] * inv1);
        }
    }
}

// ---------------------------------------------------------------------------
extern "C" void kernel_launch(void* const* d_in, const int* in_sizes, int n_in,
                              void* d_out, int out_size)
{
    const float* xq    = (const float*)d_in[0];
    const float* xk    = (const float*)d_in[1];
    const float* xv    = (const float*)d_in[2];
    const float* kvbuf = (const float*)d_in[3];
    const int*   sel   = (const int*)d_in[4];
    float* out = (float*)d_out;

    const size_t attn_elems = (size_t)PB * PS * PHQ * PD;          // 8388608
    const size_t kv_elems   = (size_t)PB * PS * 2 * PHKV * PD;     // 4194304

    cudaFuncSetAttribute(attn_kernel,
                         cudaFuncAttributeMaxDynamicSharedMemorySize,
                         SMEM_BYTES);

    // 1) kv-cache base copy (covers rows not hit by the scatter)
    float* kv_out = out + attn_elems;
    cudaMemcpyAsync(kv_out, kvbuf, kv_elems * sizeof(float),
                    cudaMemcpyDeviceToDevice);

    // 2) fused scatter + fp16 convert (one pass over xk/xv)
    {
        int total4 = PB * PS * 512;
        kv_scatter_h_kernel<<<(total4 + 255) / 256, 256>>>(xk, xv, sel, kv_out);
    }

    // 3) attention (consumes the fp16 scratch)
    dim3 grid(PS / BM, PHQ, PB);
    attn_kernel<<<grid, NT, SMEM_BYTES>>>(xq, out);
}